// round 2
// baseline (speedup 1.0000x reference)
#include <cuda_runtime.h>
#include <cuda_bf16.h>

// Problem constants (from reference)
#define N_NODES 50000
#define N_EDGES 800000
#define IN_FT   256
#define OUT_FT  128

// Scratch: seq_fts intermediate [N_NODES, OUT_FT] (25.6 MB) as static device array
__device__ float g_fts[(size_t)N_NODES * OUT_FT];

// ---------------------------------------------------------------------------
// GEMM: fts[n][o] = sum_k seq[n][k] * W[o][k]
// Tile: BM=64, BN=128 (full OUT), BK=32. 256 threads, each computes 8x4.
// ---------------------------------------------------------------------------
#define BM 64
#define BN 128
#define BK 32

__global__ __launch_bounds__(256) void gemm_kernel(
    const float* __restrict__ seq,   // [N_NODES, IN_FT]
    const float* __restrict__ W,     // [OUT_FT, IN_FT]
    float* __restrict__ fts)         // [N_NODES, OUT_FT]
{
    __shared__ float As[BK][BM + 4];
    __shared__ float Bs[BK][BN + 4];

    const int tid     = threadIdx.x;
    const int block_m = blockIdx.x * BM;
    const int row_t   = tid >> 5;   // 0..7  (8 thread-rows x 8 M-rows)
    const int col_t   = tid & 31;   // 0..31 (32 thread-cols x 4 N-cols)

    float acc[8][4];
#pragma unroll
    for (int i = 0; i < 8; i++)
#pragma unroll
        for (int j = 0; j < 4; j++) acc[i][j] = 0.0f;

    for (int k0 = 0; k0 < IN_FT; k0 += BK) {
        // Load A tile: 64 rows x 32 k = 512 float4, 2 per thread
#pragma unroll
        for (int t = 0; t < 2; t++) {
            int idx = tid + t * 256;
            int row = idx >> 3;          // 8 float4 per row
            int kq  = idx & 7;
            int g_row = block_m + row;
            float4 v = make_float4(0.f, 0.f, 0.f, 0.f);
            if (g_row < N_NODES)
                v = *reinterpret_cast<const float4*>(&seq[(size_t)g_row * IN_FT + k0 + kq * 4]);
            As[kq * 4 + 0][row] = v.x;
            As[kq * 4 + 1][row] = v.y;
            As[kq * 4 + 2][row] = v.z;
            As[kq * 4 + 3][row] = v.w;
        }
        // Load B tile: 128 rows x 32 k = 1024 float4, 4 per thread
#pragma unroll
        for (int t = 0; t < 4; t++) {
            int idx = tid + t * 256;
            int row = idx >> 3;
            int kq  = idx & 7;
            float4 v = *reinterpret_cast<const float4*>(&W[(size_t)row * IN_FT + k0 + kq * 4]);
            Bs[kq * 4 + 0][row] = v.x;
            Bs[kq * 4 + 1][row] = v.y;
            Bs[kq * 4 + 2][row] = v.z;
            Bs[kq * 4 + 3][row] = v.w;
        }
        __syncthreads();

#pragma unroll
        for (int k = 0; k < BK; k++) {
            float4 a0 = *reinterpret_cast<const float4*>(&As[k][row_t * 8]);
            float4 a1 = *reinterpret_cast<const float4*>(&As[k][row_t * 8 + 4]);
            float4 b  = *reinterpret_cast<const float4*>(&Bs[k][col_t * 4]);
            float a[8] = {a0.x, a0.y, a0.z, a0.w, a1.x, a1.y, a1.z, a1.w};
#pragma unroll
            for (int i = 0; i < 8; i++) {
                acc[i][0] += a[i] * b.x;
                acc[i][1] += a[i] * b.y;
                acc[i][2] += a[i] * b.z;
                acc[i][3] += a[i] * b.w;
            }
        }
        __syncthreads();
    }

    // Store 8x4 per thread as float4
#pragma unroll
    for (int i = 0; i < 8; i++) {
        int g_row = block_m + row_t * 8 + i;
        if (g_row < N_NODES) {
            float4 v = make_float4(acc[i][0], acc[i][1], acc[i][2], acc[i][3]);
            *reinterpret_cast<float4*>(&fts[(size_t)g_row * OUT_FT + col_t * 4]) = v;
        }
    }
}

// ---------------------------------------------------------------------------
// Scatter: one warp per edge. Lane l handles 4 contiguous floats.
// out[dst*128 + 4l .. +3] += val * fts[src*128 + 4l .. +3]
// NOTE: edge indices are int32 (JAX coerces int64->int32 without x64 mode).
// ---------------------------------------------------------------------------
__global__ __launch_bounds__(256) void scatter_kernel(
    const int*   __restrict__ edge_src,
    const int*   __restrict__ edge_dst,
    const float* __restrict__ edge_val,
    const float* __restrict__ fts,
    float*       __restrict__ out)
{
    int warp = (blockIdx.x * blockDim.x + threadIdx.x) >> 5;
    int lane = threadIdx.x & 31;
    if (warp >= N_EDGES) return;

    int   s = edge_src[warp];
    int   d = edge_dst[warp];
    float v = edge_val[warp];

    float4 m = *reinterpret_cast<const float4*>(&fts[(size_t)s * OUT_FT + lane * 4]);
    float* o = &out[(size_t)d * OUT_FT + lane * 4];
    atomicAdd(o + 0, m.x * v);
    atomicAdd(o + 1, m.y * v);
    atomicAdd(o + 2, m.z * v);
    atomicAdd(o + 3, m.w * v);
}

// ---------------------------------------------------------------------------
// Epilogue: out = prelu(out + bias)
// ---------------------------------------------------------------------------
__global__ __launch_bounds__(256) void prelu_kernel(
    float* __restrict__ out,
    const float* __restrict__ bias,
    const float* __restrict__ prelu_a)
{
    const float a = prelu_a[0];
    size_t i = (size_t)blockIdx.x * blockDim.x + threadIdx.x;   // float4 index
    size_t total4 = (size_t)N_NODES * OUT_FT / 4;
    if (i >= total4) return;
    float4 x = reinterpret_cast<float4*>(out)[i];
    float4 b = *reinterpret_cast<const float4*>(&bias[(i * 4) & (OUT_FT - 1)]);
    x.x += b.x; x.y += b.y; x.z += b.z; x.w += b.w;
    x.x = x.x >= 0.f ? x.x : a * x.x;
    x.y = x.y >= 0.f ? x.y : a * x.y;
    x.z = x.z >= 0.f ? x.z : a * x.z;
    x.w = x.w >= 0.f ? x.w : a * x.w;
    reinterpret_cast<float4*>(out)[i] = x;
}

// ---------------------------------------------------------------------------
// kernel_launch: GEMM -> zero out -> scatter -> prelu
// Inputs (metadata order): seq, edge_src(i32), edge_dst(i32), edge_val, W, bias, prelu_a
// ---------------------------------------------------------------------------
extern "C" void kernel_launch(void* const* d_in, const int* in_sizes, int n_in,
                              void* d_out, int out_size)
{
    const float* seq      = (const float*)d_in[0];
    const int*   edge_src = (const int*)d_in[1];
    const int*   edge_dst = (const int*)d_in[2];
    const float* edge_val = (const float*)d_in[3];
    const float* W        = (const float*)d_in[4];
    const float* bias     = (const float*)d_in[5];
    const float* prelu_a  = (const float*)d_in[6];
    float*       out      = (float*)d_out;

    float* fts = nullptr;
    cudaGetSymbolAddress((void**)&fts, g_fts);

    // 1) GEMM
    int gemm_blocks = (N_NODES + BM - 1) / BM;   // 782
    gemm_kernel<<<gemm_blocks, 256>>>(seq, W, fts);

    // 2) zero output (graph-capturable memset node)
    cudaMemsetAsync(out, 0, (size_t)N_NODES * OUT_FT * sizeof(float));

    // 3) scatter-add (one warp per edge)
    int warps_per_block = 256 / 32;
    int scatter_blocks = (N_EDGES + warps_per_block - 1) / warps_per_block;  // 100000
    scatter_kernel<<<scatter_blocks, 256>>>(edge_src, edge_dst, edge_val, fts, out);

    // 4) bias + PReLU
    size_t total4 = (size_t)N_NODES * OUT_FT / 4;
    int prelu_blocks = (int)((total4 + 255) / 256);
    prelu_kernel<<<prelu_blocks, 256>>>(out, bias, prelu_a);
}

// round 3
// speedup vs baseline: 1.5512x; 1.5512x over previous
#include <cuda_runtime.h>
#include <cuda_bf16.h>

// Problem constants (from reference)
#define N_NODES 50000
#define N_EDGES 800000
#define IN_FT   256
#define OUT_FT  128

// Scratch: seq_fts intermediate [N_NODES, OUT_FT] (25.6 MB)
__device__ float g_fts[(size_t)N_NODES * OUT_FT];

// ---------------------------------------------------------------------------
// GEMM: fts[n][o] = sum_k seq[n][k] * W[o][k]   (unchanged from R2: 94.5us)
// ---------------------------------------------------------------------------
#define BM 64
#define BN 128
#define BK 32

__global__ __launch_bounds__(256) void gemm_kernel(
    const float* __restrict__ seq,   // [N_NODES, IN_FT]
    const float* __restrict__ W,     // [OUT_FT, IN_FT]
    float* __restrict__ fts)         // [N_NODES, OUT_FT]
{
    __shared__ float As[BK][BM + 4];
    __shared__ float Bs[BK][BN + 4];

    const int tid     = threadIdx.x;
    const int block_m = blockIdx.x * BM;
    const int row_t   = tid >> 5;
    const int col_t   = tid & 31;

    float acc[8][4];
#pragma unroll
    for (int i = 0; i < 8; i++)
#pragma unroll
        for (int j = 0; j < 4; j++) acc[i][j] = 0.0f;

    for (int k0 = 0; k0 < IN_FT; k0 += BK) {
#pragma unroll
        for (int t = 0; t < 2; t++) {
            int idx = tid + t * 256;
            int row = idx >> 3;
            int kq  = idx & 7;
            int g_row = block_m + row;
            float4 v = make_float4(0.f, 0.f, 0.f, 0.f);
            if (g_row < N_NODES)
                v = *reinterpret_cast<const float4*>(&seq[(size_t)g_row * IN_FT + k0 + kq * 4]);
            As[kq * 4 + 0][row] = v.x;
            As[kq * 4 + 1][row] = v.y;
            As[kq * 4 + 2][row] = v.z;
            As[kq * 4 + 3][row] = v.w;
        }
#pragma unroll
        for (int t = 0; t < 4; t++) {
            int idx = tid + t * 256;
            int row = idx >> 3;
            int kq  = idx & 7;
            float4 v = *reinterpret_cast<const float4*>(&W[(size_t)row * IN_FT + k0 + kq * 4]);
            Bs[kq * 4 + 0][row] = v.x;
            Bs[kq * 4 + 1][row] = v.y;
            Bs[kq * 4 + 2][row] = v.z;
            Bs[kq * 4 + 3][row] = v.w;
        }
        __syncthreads();

#pragma unroll
        for (int k = 0; k < BK; k++) {
            float4 a0 = *reinterpret_cast<const float4*>(&As[k][row_t * 8]);
            float4 a1 = *reinterpret_cast<const float4*>(&As[k][row_t * 8 + 4]);
            float4 b  = *reinterpret_cast<const float4*>(&Bs[k][col_t * 4]);
            float a[8] = {a0.x, a0.y, a0.z, a0.w, a1.x, a1.y, a1.z, a1.w};
#pragma unroll
            for (int i = 0; i < 8; i++) {
                acc[i][0] += a[i] * b.x;
                acc[i][1] += a[i] * b.y;
                acc[i][2] += a[i] * b.z;
                acc[i][3] += a[i] * b.w;
            }
        }
        __syncthreads();
    }

#pragma unroll
    for (int i = 0; i < 8; i++) {
        int g_row = block_m + row_t * 8 + i;
        if (g_row < N_NODES) {
            float4 v = make_float4(acc[i][0], acc[i][1], acc[i][2], acc[i][3]);
            *reinterpret_cast<float4*>(&fts[(size_t)g_row * OUT_FT + col_t * 4]) = v;
        }
    }
}

// ---------------------------------------------------------------------------
// Scatter: one warp per edge, lane l handles 4 contiguous floats via ONE
// vector reduction (red.global.add.v4.f32) instead of 4 scalar atomics.
// ---------------------------------------------------------------------------
__device__ __forceinline__ void red_add_v4(float* ptr, float x, float y, float z, float w) {
    asm volatile("red.global.add.v4.f32 [%0], {%1, %2, %3, %4};"
                 :: "l"(ptr), "f"(x), "f"(y), "f"(z), "f"(w)
                 : "memory");
}

__global__ __launch_bounds__(256) void scatter_kernel(
    const int*   __restrict__ edge_src,
    const int*   __restrict__ edge_dst,
    const float* __restrict__ edge_val,
    const float* __restrict__ fts,
    float*       __restrict__ out)
{
    int warp = (blockIdx.x * blockDim.x + threadIdx.x) >> 5;
    int lane = threadIdx.x & 31;
    if (warp >= N_EDGES) return;

    int   s = edge_src[warp];
    int   d = edge_dst[warp];
    float v = edge_val[warp];

    float4 m = *reinterpret_cast<const float4*>(&fts[(size_t)s * OUT_FT + lane * 4]);
    float* o = &out[(size_t)d * OUT_FT + lane * 4];
    red_add_v4(o, m.x * v, m.y * v, m.z * v, m.w * v);
}

// ---------------------------------------------------------------------------
// Epilogue: out = prelu(out + bias)
// ---------------------------------------------------------------------------
__global__ __launch_bounds__(256) void prelu_kernel(
    float* __restrict__ out,
    const float* __restrict__ bias,
    const float* __restrict__ prelu_a)
{
    const float a = prelu_a[0];
    size_t i = (size_t)blockIdx.x * blockDim.x + threadIdx.x;   // float4 index
    size_t total4 = (size_t)N_NODES * OUT_FT / 4;
    if (i >= total4) return;
    float4 x = reinterpret_cast<float4*>(out)[i];
    float4 b = *reinterpret_cast<const float4*>(&bias[(i * 4) & (OUT_FT - 1)]);
    x.x += b.x; x.y += b.y; x.z += b.z; x.w += b.w;
    x.x = x.x >= 0.f ? x.x : a * x.x;
    x.y = x.y >= 0.f ? x.y : a * x.y;
    x.z = x.z >= 0.f ? x.z : a * x.z;
    x.w = x.w >= 0.f ? x.w : a * x.w;
    reinterpret_cast<float4*>(out)[i] = x;
}

// ---------------------------------------------------------------------------
// kernel_launch: GEMM -> zero out -> scatter -> prelu
// Inputs: seq, edge_src(i32), edge_dst(i32), edge_val, W, bias, prelu_a
// ---------------------------------------------------------------------------
extern "C" void kernel_launch(void* const* d_in, const int* in_sizes, int n_in,
                              void* d_out, int out_size)
{
    const float* seq      = (const float*)d_in[0];
    const int*   edge_src = (const int*)d_in[1];
    const int*   edge_dst = (const int*)d_in[2];
    const float* edge_val = (const float*)d_in[3];
    const float* W        = (const float*)d_in[4];
    const float* bias     = (const float*)d_in[5];
    const float* prelu_a  = (const float*)d_in[6];
    float*       out      = (float*)d_out;

    float* fts = nullptr;
    cudaGetSymbolAddress((void**)&fts, g_fts);

    int gemm_blocks = (N_NODES + BM - 1) / BM;
    gemm_kernel<<<gemm_blocks, 256>>>(seq, W, fts);

    cudaMemsetAsync(out, 0, (size_t)N_NODES * OUT_FT * sizeof(float));

    int warps_per_block = 256 / 32;
    int scatter_blocks = (N_EDGES + warps_per_block - 1) / warps_per_block;
    scatter_kernel<<<scatter_blocks, 256>>>(edge_src, edge_dst, edge_val, fts, out);

    size_t total4 = (size_t)N_NODES * OUT_FT / 4;
    int prelu_blocks = (int)((total4 + 255) / 256);
    prelu_kernel<<<prelu_blocks, 256>>>(out, bias, prelu_a);
}